// round 14
// baseline (speedup 1.0000x reference)
#include <cuda_runtime.h>
#include <cuda_bf16.h>
#include <cstdint>

#define NROWS 16384
#define KDIM  4096
#define ODIM  4096

#if defined(__CUDA_ARCH_FEAT_SM103_ALL) || defined(__CUDA_ARCH_FEAT_SM100_ALL) || \
    defined(__CUDA_ARCH_SPECIFIC__) || defined(__CUDA_ARCH_FAMILY_SPECIFIC__)
#define HAS_TCGEN05 1
#else
#define HAS_TCGEN05 0
#endif

// ---------------- scratch: TILED-SWIZZLED bf16 operands ----------------
// Block (tile, kstage) = 32 KB contiguous: 256 rows x 128B, row SW128-swizzled.
__device__ unsigned char g_qxt[(size_t)NROWS * KDIM * 2];   // 128 MB
__device__ unsigned char g_qwt[(size_t)ODIM * KDIM * 2];    // 32 MB
__device__ float g_wscale[ODIM];
__device__ unsigned int g_xmax_u, g_xmin_u, g_rmax_u, g_rmin_u;
__device__ float g_sc, g_zp, g_resc, g_rezp;

// ---------------- PTX helpers ----------------
__device__ __forceinline__ uint32_t smem_u32(const void* p) {
    uint32_t a;
    asm("{ .reg .u64 t; cvta.to.shared.u64 t, %1; cvt.u32.u64 %0, t; }" : "=r"(a) : "l"(p));
    return a;
}
__device__ __forceinline__ uint32_t cluster_rank() {
    uint32_t r;
    asm("mov.u32 %0, %%cluster_ctarank;" : "=r"(r));
    return r;
}
#define TCGEN05_ALLOC_CG2(sm, n) \
    asm volatile("tcgen05.alloc.cta_group::2.sync.aligned.shared::cta.b32 [%0], %1;" \
                 :: "r"((uint32_t)(sm)), "r"((uint32_t)(n)) : "memory")
#define TCGEN05_DEALLOC_CG2(t, n) \
    asm volatile("tcgen05.dealloc.cta_group::2.sync.aligned.b32 %0, %1;" :: "r"(t), "r"((uint32_t)(n)))
#define TCGEN05_RELINQ_CG2() \
    asm volatile("tcgen05.relinquish_alloc_permit.cta_group::2.sync.aligned;")
#define TCGEN05_COMMIT_MC_CG2(mb, mask) \
    asm volatile("tcgen05.commit.cta_group::2.mbarrier::arrive::one.shared::cluster.multicast::cluster.b64 [%0], %1;" \
                 :: "r"((uint32_t)(mb)), "h"((uint16_t)(mask)) : "memory")
#define TCGEN05_FENCE_AFTER()  asm volatile("tcgen05.fence::after_thread_sync;" ::: "memory")
#define TCGEN05_FENCE_BEFORE() asm volatile("tcgen05.fence::before_thread_sync;" ::: "memory")
#define TCGEN05_WAIT_LD()      asm volatile("tcgen05.wait::ld.sync.aligned;" ::: "memory")
#define MBAR_INIT(a, c) \
    asm volatile("mbarrier.init.shared.b64 [%0], %1;" :: "r"((uint32_t)(a)), "r"((uint32_t)(c)) : "memory")
#define MBAR_EXPECT_TX(a, n) \
    asm volatile("mbarrier.arrive.expect_tx.shared.b64 _, [%0], %1;" :: "r"((uint32_t)(a)), "r"((uint32_t)(n)) : "memory")
#define MBAR_ARRIVE_CLUSTER(addr, rank) \
    asm volatile( \
        "{\n\t.reg .b32 remAddr32;\n\t" \
        "mapa.shared::cluster.u32 remAddr32, %0, %1;\n\t" \
        "mbarrier.arrive.shared::cluster.b64 _, [remAddr32];\n\t}" \
        :: "r"((uint32_t)(addr)), "r"((uint32_t)(rank)) : "memory")
#define CLUSTER_ARRIVE() asm volatile("barrier.cluster.arrive.aligned;" ::: "memory")
#define CLUSTER_WAIT()   asm volatile("barrier.cluster.wait.aligned;" ::: "memory")

#define MBAR_WAIT_PARITY(mb, par) do {                                            \
    uint32_t _m = (uint32_t)(mb); uint32_t _p = (uint32_t)(par);                  \
    asm volatile(                                                                 \
        "{\n\t.reg .pred P1;\n\t"                                                 \
        "WL_%=:\n\t"                                                              \
        "mbarrier.try_wait.parity.acquire.cta.shared::cta.b64 P1, [%0], %1, 0x989680;\n\t" \
        "@P1 bra.uni WD_%=;\n\t"                                                  \
        "bra.uni WL_%=;\n\t"                                                      \
        "WD_%=:\n\t}"                                                             \
        :: "r"(_m), "r"(_p) : "memory");                                          \
} while (0)

#define TCGEN05_LD_X32(r, addr) \
    asm volatile( \
        "tcgen05.ld.sync.aligned.32x32b.x32.b32 " \
        "{%0, %1, %2, %3, %4, %5, %6, %7, " \
        " %8, %9, %10, %11, %12, %13, %14, %15, " \
        " %16, %17, %18, %19, %20, %21, %22, %23, " \
        " %24, %25, %26, %27, %28, %29, %30, %31}, [%32];" \
        : "=r"((r)[0]),  "=r"((r)[1]),  "=r"((r)[2]),  "=r"((r)[3]), \
          "=r"((r)[4]),  "=r"((r)[5]),  "=r"((r)[6]),  "=r"((r)[7]), \
          "=r"((r)[8]),  "=r"((r)[9]),  "=r"((r)[10]), "=r"((r)[11]), \
          "=r"((r)[12]), "=r"((r)[13]), "=r"((r)[14]), "=r"((r)[15]), \
          "=r"((r)[16]), "=r"((r)[17]), "=r"((r)[18]), "=r"((r)[19]), \
          "=r"((r)[20]), "=r"((r)[21]), "=r"((r)[22]), "=r"((r)[23]), \
          "=r"((r)[24]), "=r"((r)[25]), "=r"((r)[26]), "=r"((r)[27]), \
          "=r"((r)[28]), "=r"((r)[29]), "=r"((r)[30]), "=r"((r)[31]) \
        : "r"(addr))

#if HAS_TCGEN05
__device__ __forceinline__ void bulk_cp(uint32_t dst, const void* src, uint32_t bytes,
                                        uint32_t mbar) {
    asm volatile(
        "cp.async.bulk.shared::cluster.global.mbarrier::complete_tx::bytes "
        "[%0], [%1], %2, [%3];"
        :: "r"(dst), "l"(src), "r"(bytes), "r"(mbar) : "memory");
}
#endif

// SW128 K-major descriptor (layout=2, version=1, SBO=64, LBO=1) — 128B rows
__device__ __forceinline__ uint64_t make_desc(uint32_t addr) {
    return ((uint64_t)2 << 61) | ((uint64_t)1 << 46) | ((uint64_t)64 << 32) |
           ((uint64_t)1 << 16) | ((addr >> 4) & 0x3FFF);
}

// idesc kind::f16 cg2: dtype=F32(bit4), atype=BF16(bit7), btype=BF16(bit10),
// N=256 (32<<17), M=256 (16<<24)
#define GEMM_IDESC2 ((1u << 4) | (1u << 7) | (1u << 10) | (32u << 17) | (16u << 24))

__device__ __forceinline__ void mma_f16_ss_cg2(uint32_t d, uint64_t ad, uint64_t bd,
                                               uint32_t idesc, bool acc) {
    uint32_t e = acc ? 1u : 0u;
    asm volatile(
        "{\n\t.reg .pred p;\n\t"
        "setp.ne.u32 p, %5, 0;\n\t"
        "tcgen05.mma.cta_group::2.kind::f16 [%0], %1, %2, %3, "
        "{%4,%4,%4,%4,%4,%4,%4,%4}, p;\n\t"
        "}"
        :: "r"(d), "l"(ad), "l"(bd), "r"(idesc), "r"(0u), "r"(e) : "memory");
}

// ---------------- misc kernels (unchanged from round 13) ----------------
__global__ void init_kernel() {
    g_xmax_u = 0u; g_xmin_u = 0u; g_rmax_u = 0u; g_rmin_u = 0u;
}

__device__ __forceinline__ void block_minmax_atomic(float tmn, float tmx,
                                                    unsigned int* gmin, unsigned int* gmax) {
    #pragma unroll
    for (int o = 16; o > 0; o >>= 1) {
        tmx = fmaxf(tmx, __shfl_xor_sync(0xffffffffu, tmx, o));
        tmn = fminf(tmn, __shfl_xor_sync(0xffffffffu, tmn, o));
    }
    __shared__ float smx[32], smn[32];
    int w = threadIdx.x >> 5, nw = blockDim.x >> 5;
    if ((threadIdx.x & 31) == 0) { smx[w] = tmx; smn[w] = tmn; }
    __syncthreads();
    if (threadIdx.x == 0) {
        for (int i = 1; i < nw; i++) { tmx = fmaxf(tmx, smx[i]); tmn = fminf(tmn, smn[i]); }
        atomicMax(gmax, __float_as_uint(fmaxf(tmx, 0.f)));
        atomicMax(gmin, __float_as_uint(fminf(tmn, 0.f)));
    }
}

__device__ __forceinline__ size_t tiled_off(int row, int k) {
    int tile = row >> 8, r = row & 255, ks = k >> 6;
    int c16 = (k & 63) >> 3, half = (k >> 2) & 1;
    return ((((size_t)tile * (KDIM / 64) + ks) * 256 + r) << 7) +
           (size_t)(((c16 ^ (r & 7)) << 4) + (half << 3));
}

#define MMX_BLOCKS 2048
__global__ void quantw_minmax_kernel(const float* __restrict__ w,
                                     const float4* __restrict__ x4, int n4) {
    if (blockIdx.x >= ODIM) {
        int mb = blockIdx.x - ODIM;
        float tmx = 0.f, tmn = 0.f;
        for (int i = mb * blockDim.x + threadIdx.x; i < n4; i += MMX_BLOCKS * blockDim.x) {
            float4 v = x4[i];
            tmx = fmaxf(tmx, fmaxf(fmaxf(v.x, v.y), fmaxf(v.z, v.w)));
            tmn = fminf(tmn, fminf(fminf(v.x, v.y), fminf(v.z, v.w)));
        }
        block_minmax_atomic(tmn, tmx, &g_xmin_u, &g_xmax_u);
        return;
    }
    int row = blockIdx.x;
    const float4* wr = (const float4*)(w + (size_t)row * KDIM);
    float4 v[4];
    float am = 0.f;
    #pragma unroll
    for (int i = 0; i < 4; i++) {
        v[i] = wr[threadIdx.x + i * 256];
        am = fmaxf(am, fmaxf(fmaxf(fabsf(v[i].x), fabsf(v[i].y)),
                             fmaxf(fabsf(v[i].z), fabsf(v[i].w))));
    }
    #pragma unroll
    for (int o = 16; o > 0; o >>= 1) am = fmaxf(am, __shfl_xor_sync(0xffffffffu, am, o));
    __shared__ float sred[8];
    __shared__ float swsv;
    if ((threadIdx.x & 31) == 0) sred[threadIdx.x >> 5] = am;
    __syncthreads();
    if (threadIdx.x == 0) {
        for (int i = 1; i < 8; i++) am = fmaxf(am, sred[i]);
        float ws = am / 127.f;
        swsv = ws;
        g_wscale[row] = ws;
    }
    __syncthreads();
    float ws = swsv;
    #pragma unroll
    for (int i = 0; i < 4; i++) {
        int k = (threadIdx.x + i * 256) * 4;
        float q0 = fminf(fmaxf(rintf(v[i].x / ws), -127.f), 127.f);
        float q1 = fminf(fmaxf(rintf(v[i].y / ws), -127.f), 127.f);
        float q2 = fminf(fmaxf(rintf(v[i].z / ws), -127.f), 127.f);
        float q3 = fminf(fmaxf(rintf(v[i].w / ws), -127.f), 127.f);
        __nv_bfloat162 p0, p1;
        p0.x = __float2bfloat16_rn(q0); p0.y = __float2bfloat16_rn(q1);
        p1.x = __float2bfloat16_rn(q2); p1.y = __float2bfloat16_rn(q3);
        uint2 pk;
        pk.x = *(uint32_t*)&p0; pk.y = *(uint32_t*)&p1;
        *(uint2*)(g_qwt + tiled_off(row, k)) = pk;
    }
}

__global__ void params1_kernel() {
    float mx = __uint_as_float(g_xmax_u);
    float mn = __uint_as_float(g_xmin_u);
    float sc = (mx - mn) / 255.f;
    g_sc = sc;
    g_zp = rintf(-128.f - mn / sc);
}

__global__ void quantx_kernel(const float4* __restrict__ x4, int n4) {
    float sc = g_sc, zp = g_zp;
    for (int i = blockIdx.x * blockDim.x + threadIdx.x; i < n4; i += gridDim.x * blockDim.x) {
        float4 v = x4[i];
        int e = i * 4;
        int row = e >> 12, k = e & (KDIM - 1);
        float q0 = fminf(fmaxf(rintf(v.x / sc) + zp, -128.f), 127.f) - zp;
        float q1 = fminf(fmaxf(rintf(v.y / sc) + zp, -128.f), 127.f) - zp;
        float q2v = fminf(fmaxf(rintf(v.z / sc) + zp, -128.f), 127.f) - zp;
        float q3 = fminf(fmaxf(rintf(v.w / sc) + zp, -128.f), 127.f) - zp;
        __nv_bfloat162 p0, p1;
        p0.x = __float2bfloat16_rn(q0);  p0.y = __float2bfloat16_rn(q1);
        p1.x = __float2bfloat16_rn(q2v); p1.y = __float2bfloat16_rn(q3);
        uint2 pk;
        pk.x = *(uint32_t*)&p0; pk.y = *(uint32_t*)&p1;
        *(uint2*)(g_qxt + tiled_off(row, k)) = pk;
    }
}

// ===== cg2 tcgen05 GEMM: pair tile 256(M) x 512(N), BK=64, 3 stages =====
// Per CTA per stage: A-half 16KB @+0, B-inst0 half 16KB @+16384, B-inst1 half 16KB @+32768.
// Leader (rank 0) issues 2 N=256 MMA insts x 4 K-steps; commit multicast to both
// CTAs' empty bars. Follower signals data-ready via cluster arrive on leader's
// peer-full bar after its own full bar fires.
#define STAGES 3
#define STAGE_BYTES 49152
#define SMEM_STAGE0 1024
#define SMEM_FULLB 8
#define SMEM_EMPTYB 32
#define SMEM_PEERFB 64
#define SMEM_QB (SMEM_STAGE0 + STAGES * STAGE_BYTES)
#define GEMM_SMEM (SMEM_QB + 512 * 4)
#define NKITER (KDIM / 64)

__global__ void __launch_bounds__(256, 1) __cluster_dims__(2, 1, 1)
gemm_tc_kernel(const float* __restrict__ bias, float* __restrict__ out) {
#if HAS_TCGEN05
    extern __shared__ __align__(1024) char ds[];
    uint32_t sb = smem_u32(ds);
    int tid = threadIdx.x, wid = tid >> 5, lane = tid & 31;
    int bx = blockIdx.x, by = blockIdx.y;
    uint32_t rank = cluster_rank();
    int bx0 = bx & ~1;
    int bm = by * 256;
    int bnp = bx0 * 256;                       // pair col base (512 wide)

    if (wid == 0) TCGEN05_ALLOC_CG2(sb + 0, 512);
    if (tid == 0) {
        #pragma unroll
        for (int s = 0; s < STAGES; s++) {
            MBAR_INIT(sb + SMEM_FULLB + s * 8, 1);
            MBAR_INIT(sb + SMEM_EMPTYB + s * 8, 1);   // leader's multicast commit
            MBAR_INIT(sb + SMEM_PEERFB + s * 8, 1);   // follower's cluster arrive
        }
    }
    __syncthreads();
    uint32_t tb;
    asm volatile("ld.shared.b32 %0, [%1];" : "=r"(tb) : "r"(sb));

    CLUSTER_ARRIVE();
    CLUSTER_WAIT();

    if (tid == 0) {
        size_t roff = (size_t)rank * 16384;
        const unsigned char* Ab  = g_qxt + ((size_t)by * NKITER) * 32768 + roff;
        const unsigned char* Bb0 = g_qwt + ((size_t)bx0 * NKITER) * 32768 + roff;
        const unsigned char* Bb1 = g_qwt + ((size_t)(bx0 + 1) * NKITER) * 32768 + roff;

        // prologue: stages 0,1
        #pragma unroll
        for (int s = 0; s < STAGES - 1; s++) {
            uint32_t stg = sb + SMEM_STAGE0 + s * STAGE_BYTES;
            uint32_t fb = sb + SMEM_FULLB + s * 8;
            MBAR_EXPECT_TX(fb, STAGE_BYTES);
            bulk_cp(stg,         Ab  + (size_t)s * 32768, 16384, fb);
            bulk_cp(stg + 16384, Bb0 + (size_t)s * 32768, 16384, fb);
            bulk_cp(stg + 32768, Bb1 + (size_t)s * 32768, 16384, fb);
        }

        int f0 = 0, f1 = 0, f2 = 0, e0 = 0, e1 = 0, e2 = 0, p0 = 0, p1 = 0, p2 = 0;
        for (int k0 = 0; k0 < NKITER; k0++) {
            int s = k0 % STAGES;
            uint32_t stg = sb + SMEM_STAGE0 + s * STAGE_BYTES;

            // own data ready
            uint32_t fb = sb + SMEM_FULLB + s * 8;
            int fp = (s == 0) ? f0 : (s == 1) ? f1 : f2;
            MBAR_WAIT_PARITY(fb, fp);
            if (s == 0) f0 ^= 1; else if (s == 1) f1 ^= 1; else f2 ^= 1;

            if (rank == 0) {
                // peer data ready
                uint32_t pb = sb + SMEM_PEERFB + s * 8;
                int pp = (s == 0) ? p0 : (s == 1) ? p1 : p2;
                MBAR_WAIT_PARITY(pb, pp);
                if (s == 0) p0 ^= 1; else if (s == 1) p1 ^= 1; else p2 ^= 1;
                TCGEN05_FENCE_AFTER();

                uint64_t ad = make_desc(stg);
                #pragma unroll
                for (int j = 0; j < 2; j++) {
                    uint64_t bd = make_desc(stg + 16384 + j * 16384);
                    #pragma unroll
                    for (int kk = 0; kk < 4; kk++)
                        mma_f16_ss_cg2(tb + j * 256, ad + kk * 2, bd + kk * 2,
                                       GEMM_IDESC2, !(k0 == 0 && kk == 0));
                }
                TCGEN05_COMMIT_MC_CG2(sb + SMEM_EMPTYB + s * 8, 0x3);
            } else {
                // tell leader my stage s is loaded
                MBAR_ARRIVE_CLUSTER(sb + SMEM_PEERFB + s * 8, 0);
            }

            // prefetch k0+2; WAR signal = leader's commit of iter k0-1 (fast path)
            int kn = k0 + STAGES - 1;
            if (kn < NKITER) {
                int t = kn % STAGES;
                uint32_t tstg = sb + SMEM_STAGE0 + t * STAGE_BYTES;
                uint32_t tfb = sb + SMEM_FULLB + t * 8;
                if (k0 > 0) {
                    uint32_t teb = sb + SMEM_EMPTYB + t * 8;
                    int ep = (t == 0) ? e0 : (t == 1) ? e1 : e2;
                    MBAR_WAIT_PARITY(teb, ep);
                    if (t == 0) e0 ^= 1; else if (t == 1) e1 ^= 1; else e2 ^= 1;
                }
                MBAR_EXPECT_TX(tfb, STAGE_BYTES);
                bulk_cp(tstg,         Ab  + (size_t)kn * 32768, 16384, tfb);
                bulk_cp(tstg + 16384, Bb0 + (size_t)kn * 32768, 16384, tfb);
                bulk_cp(tstg + 32768, Bb1 + (size_t)kn * 32768, 16384, tfb);
            }
        }
        {   // final commit (multicast reaches both CTAs)
            int sl = (NKITER - 1) % STAGES;
            int ep = (sl == 0) ? e0 : (sl == 1) ? e1 : e2;
            MBAR_WAIT_PARITY(sb + SMEM_EMPTYB + sl * 8, ep);
        }
    }
    __syncthreads();
    TCGEN05_FENCE_AFTER();

    // qbias for the pair's 512 cols
    float sc = g_sc;
    float* qb = (float*)(ds + SMEM_QB);
    {
        int c0 = bnp + tid * 2;
        qb[tid * 2]     = rintf(bias[c0]     / (g_wscale[c0]     * sc));
        qb[tid * 2 + 1] = rintf(bias[c0 + 1] / (g_wscale[c0 + 1] * sc));
    }
    __syncthreads();

    // epilogue: this CTA's TMEM holds its 128 M-rows x 512 cols.
    // warps 0-3 read cols 0..255, warps 4-7 read cols 256..511 (same lane groups).
    int half = wid >> 2;
    int row = bm + (int)rank * 128 + (wid & 3) * 32 + lane;
    int colbase = half * 256;
    float tmx = 0.f, tmn = 0.f;
    float* orow = out + (size_t)row * ODIM + bnp + colbase;
    #pragma unroll
    for (int ch = 0; ch < 8; ch++) {
        uint32_t dr[32];
        TCGEN05_LD_X32(dr, tb + colbase + ch * 32);
        TCGEN05_WAIT_LD();
        float v[32];
        #pragma unroll
        for (int c = 0; c < 32; c++) {
            float f = __uint_as_float(dr[c]) + qb[colbase + ch * 32 + c];
            v[c] = f;
            tmx = fmaxf(tmx, f);
            tmn = fminf(tmn, f);
        }
        #pragma unroll
        for (int c = 0; c < 32; c += 4)
            *(float4*)&orow[ch * 32 + c] = make_float4(v[c], v[c + 1], v[c + 2], v[c + 3]);
    }
    TCGEN05_FENCE_BEFORE();
    block_minmax_atomic(tmn, tmx, &g_rmin_u, &g_rmax_u);
    __syncthreads();
    if (wid == 0) {
        TCGEN05_RELINQ_CG2();
        TCGEN05_DEALLOC_CG2(tb, 512);
    }
    CLUSTER_ARRIVE();
    CLUSTER_WAIT();
#endif
}

__global__ void params2_kernel() {
    float rmx = __uint_as_float(g_rmax_u);
    float rmn = __uint_as_float(g_rmin_u);
    float resc = (rmx - rmn) / 255.f;
    g_resc = resc;
    g_rezp = rintf(-128.f - rmn / resc);
}

__global__ void requant_kernel(float4* __restrict__ out4, int n4) {
    float resc = g_resc, rezp = g_rezp, sc = g_sc;
    for (int i = blockIdx.x * blockDim.x + threadIdx.x; i < n4; i += gridDim.x * blockDim.x) {
        float4 v = out4[i];
        int col = (i * 4) & (ODIM - 1);
        float s0 = (sc * g_wscale[col])     * resc;
        float s1 = (sc * g_wscale[col + 1]) * resc;
        float s2 = (sc * g_wscale[col + 2]) * resc;
        float s3 = (sc * g_wscale[col + 3]) * resc;
        float r0 = fminf(fmaxf(rintf(v.x / resc) + rezp, -128.f), 127.f);
        float r1 = fminf(fmaxf(rintf(v.y / resc) + rezp, -128.f), 127.f);
        float r2 = fminf(fmaxf(rintf(v.z / resc) + rezp, -128.f), 127.f);
        float r3 = fminf(fmaxf(rintf(v.w / resc) + rezp, -128.f), 127.f);
        v.x = (r0 - rezp) * s0;
        v.y = (r1 - rezp) * s1;
        v.z = (r2 - rezp) * s2;
        v.w = (r3 - rezp) * s3;
        out4[i] = v;
    }
}

// ---------------- launch ----------------
extern "C" void kernel_launch(void* const* d_in, const int* in_sizes, int n_in,
                              void* d_out, int out_size) {
    const float* x    = (const float*)d_in[0];
    const float* w    = (const float*)d_in[1];
    const float* bias = (const float*)d_in[2];
    float* out = (float*)d_out;

    cudaFuncSetAttribute(gemm_tc_kernel, cudaFuncAttributeMaxDynamicSharedMemorySize, GEMM_SMEM);

    init_kernel<<<1, 1>>>();
    quantw_minmax_kernel<<<ODIM + MMX_BLOCKS, 256>>>(w, (const float4*)x, NROWS * KDIM / 4);
    params1_kernel<<<1, 1>>>();
    quantx_kernel<<<4096, 256>>>((const float4*)x, NROWS * KDIM / 4);

    dim3 grid_tc(ODIM / 256, NROWS / 256);
    gemm_tc_kernel<<<grid_tc, 256, GEMM_SMEM>>>(bias, out);

    params2_kernel<<<1, 1>>>();
    requant_kernel<<<4096, 256>>>((float4*)out, NROWS * ODIM / 4);
}

// round 15
// speedup vs baseline: 1.0940x; 1.0940x over previous
#include <cuda_runtime.h>
#include <cuda_bf16.h>
#include <cstdint>

#define NROWS 16384
#define KDIM  4096
#define ODIM  4096

// Arch-feature guard: tcgen05 only exists in arch-specific ('a') / family targets.
#if defined(__CUDA_ARCH_FEAT_SM103_ALL) || defined(__CUDA_ARCH_FEAT_SM100_ALL) || \
    defined(__CUDA_ARCH_SPECIFIC__) || defined(__CUDA_ARCH_FAMILY_SPECIFIC__)
#define HAS_TCGEN05 1
#else
#define HAS_TCGEN05 0
#endif

// ---------------- scratch: TILED-SWIZZLED bf16 operands ----------------
// Block (tile, kstage) = 32 KB contiguous: 256 rows x 128B, each row SW128-swizzled
// (16B chunk cc at offset (cc ^ (row&7))*16). A stage is one contiguous 32KB block.
__device__ unsigned char g_qxt[(size_t)NROWS * KDIM * 2];   // 128 MB
__device__ unsigned char g_qwt[(size_t)ODIM * KDIM * 2];    // 32 MB
__device__ float g_wscale[ODIM];
__device__ unsigned int g_xmax_u, g_xmin_u, g_rmax_u, g_rmin_u;
__device__ float g_sc, g_zp, g_resc, g_rezp;

// ---------------- PTX helpers ----------------
__device__ __forceinline__ uint32_t smem_u32(const void* p) {
    uint32_t a;
    asm("{ .reg .u64 t; cvta.to.shared.u64 t, %1; cvt.u32.u64 %0, t; }" : "=r"(a) : "l"(p));
    return a;
}
#define TCGEN05_ALLOC(sm, n) \
    asm volatile("tcgen05.alloc.cta_group::1.sync.aligned.shared::cta.b32 [%0], %1;" \
                 :: "r"((uint32_t)(sm)), "r"((uint32_t)(n)) : "memory")
#define TCGEN05_DEALLOC(t, n) \
    asm volatile("tcgen05.dealloc.cta_group::1.sync.aligned.b32 %0, %1;" :: "r"(t), "r"((uint32_t)(n)))
#define TCGEN05_RELINQ() \
    asm volatile("tcgen05.relinquish_alloc_permit.cta_group::1.sync.aligned;")
#define TCGEN05_COMMIT(mb) \
    asm volatile("tcgen05.commit.cta_group::1.mbarrier::arrive::one.shared::cluster.b64 [%0];" \
                 :: "r"((uint32_t)(mb)) : "memory")
#define TCGEN05_FENCE_AFTER()  asm volatile("tcgen05.fence::after_thread_sync;" ::: "memory")
#define TCGEN05_FENCE_BEFORE() asm volatile("tcgen05.fence::before_thread_sync;" ::: "memory")
#define TCGEN05_WAIT_LD()      asm volatile("tcgen05.wait::ld.sync.aligned;" ::: "memory")
#define MBAR_INIT(a, c) \
    asm volatile("mbarrier.init.shared.b64 [%0], %1;" :: "r"((uint32_t)(a)), "r"((uint32_t)(c)) : "memory")
#define FENCE_PROXY_ASYNC() asm volatile("fence.proxy.async.shared::cta;" ::: "memory")

#define MBAR_WAIT_PARITY(mb, par) do {                                            \
    uint32_t _m = (uint32_t)(mb); uint32_t _p = (uint32_t)(par);                  \
    asm volatile(                                                                 \
        "{\n\t.reg .pred P1;\n\t"                                                 \
        "WL_%=:\n\t"                                                              \
        "mbarrier.try_wait.parity.acquire.cta.shared::cta.b64 P1, [%0], %1, 0x989680;\n\t" \
        "@P1 bra.uni WD_%=;\n\t"                                                  \
        "bra.uni WL_%=;\n\t"                                                      \
        "WD_%=:\n\t}"                                                             \
        :: "r"(_m), "r"(_p) : "memory");                                          \
} while (0)

#define TCGEN05_LD_X32(r, addr) \
    asm volatile( \
        "tcgen05.ld.sync.aligned.32x32b.x32.b32 " \
        "{%0, %1, %2, %3, %4, %5, %6, %7, " \
        " %8, %9, %10, %11, %12, %13, %14, %15, " \
        " %16, %17, %18, %19, %20, %21, %22, %23, " \
        " %24, %25, %26, %27, %28, %29, %30, %31}, [%32];" \
        : "=r"((r)[0]),  "=r"((r)[1]),  "=r"((r)[2]),  "=r"((r)[3]), \
          "=r"((r)[4]),  "=r"((r)[5]),  "=r"((r)[6]),  "=r"((r)[7]), \
          "=r"((r)[8]),  "=r"((r)[9]),  "=r"((r)[10]), "=r"((r)[11]), \
          "=r"((r)[12]), "=r"((r)[13]), "=r"((r)[14]), "=r"((r)[15]), \
          "=r"((r)[16]), "=r"((r)[17]), "=r"((r)[18]), "=r"((r)[19]), \
          "=r"((r)[20]), "=r"((r)[21]), "=r"((r)[22]), "=r"((r)[23]), \
          "=r"((r)[24]), "=r"((r)[25]), "=r"((r)[26]), "=r"((r)[27]), \
          "=r"((r)[28]), "=r"((r)[29]), "=r"((r)[30]), "=r"((r)[31]) \
        : "r"(addr))

__device__ __forceinline__ void cp16(uint32_t s, const void* g) {
    asm volatile("cp.async.cg.shared.global [%0], [%1], 16;" :: "r"(s), "l"(g));
}
#define CP_COMMIT() asm volatile("cp.async.commit_group;" ::: "memory")
#define CP_WAIT1()  asm volatile("cp.async.wait_group 1;" ::: "memory")

// SW128 K-major descriptor (layout=2, version=1, SBO=64, LBO=1) — 128B rows
__device__ __forceinline__ uint64_t make_desc(uint32_t addr) {
    return ((uint64_t)2 << 61) | ((uint64_t)1 << 46) | ((uint64_t)64 << 32) |
           ((uint64_t)1 << 16) | ((addr >> 4) & 0x3FFF);
}

// idesc kind::f16: dtype=F32(bit4), atype=BF16(bit7), btype=BF16(bit10), N=256, M=128
#define GEMM_IDESC ((1u << 4) | (1u << 7) | (1u << 10) | ((256u / 8) << 17) | ((128u / 16) << 24))

__device__ __forceinline__ void mma_f16_ss(uint32_t d, uint64_t ad, uint64_t bd,
                                           uint32_t idesc, bool acc) {
    uint32_t e = acc ? 1u : 0u;
    asm volatile(
        "{\n\t.reg .pred p;\n\t"
        "setp.ne.u32 p, %4, 0;\n\t"
        "tcgen05.mma.cta_group::1.kind::f16 [%0], %1, %2, %3, {%5,%5,%5,%5}, p;\n\t"
        "}"
        :: "r"(d), "l"(ad), "l"(bd), "r"(idesc), "r"(e), "r"(0u) : "memory");
}

// ---------------- misc kernels ----------------
__global__ void init_kernel() {
    g_xmax_u = 0u; g_xmin_u = 0u; g_rmax_u = 0u; g_rmin_u = 0u;
}

__device__ __forceinline__ void block_minmax_atomic(float tmn, float tmx,
                                                    unsigned int* gmin, unsigned int* gmax) {
    #pragma unroll
    for (int o = 16; o > 0; o >>= 1) {
        tmx = fmaxf(tmx, __shfl_xor_sync(0xffffffffu, tmx, o));
        tmn = fminf(tmn, __shfl_xor_sync(0xffffffffu, tmn, o));
    }
    __shared__ float smx[32], smn[32];
    int w = threadIdx.x >> 5, nw = blockDim.x >> 5;
    if ((threadIdx.x & 31) == 0) { smx[w] = tmx; smn[w] = tmn; }
    __syncthreads();
    if (threadIdx.x == 0) {
        for (int i = 1; i < nw; i++) { tmx = fmaxf(tmx, smx[i]); tmn = fminf(tmn, smn[i]); }
        atomicMax(gmax, __float_as_uint(fmaxf(tmx, 0.f)));
        atomicMax(gmin, __float_as_uint(fminf(tmn, 0.f)));
    }
}

// tiled-swizzled dst offset for element group (row, k..k+3) -> 8-byte slot
__device__ __forceinline__ size_t tiled_off(int row, int k) {
    int tile = row >> 8, r = row & 255, ks = k >> 6;
    int c16 = (k & 63) >> 3, half = (k >> 2) & 1;
    return ((((size_t)tile * (KDIM / 64) + ks) * 256 + r) << 7) +
           (size_t)(((c16 ^ (r & 7)) << 4) + (half << 3));
}

// FUSED: blocks [0, ODIM) quantize W rows; blocks [ODIM, ODIM+2048) reduce x min/max.
#define MMX_BLOCKS 2048
__global__ void quantw_minmax_kernel(const float* __restrict__ w,
                                     const float4* __restrict__ x4, int n4) {
    if (blockIdx.x >= ODIM) {
        int mb = blockIdx.x - ODIM;
        float tmx = 0.f, tmn = 0.f;
        for (int i = mb * blockDim.x + threadIdx.x; i < n4; i += MMX_BLOCKS * blockDim.x) {
            float4 v = x4[i];
            tmx = fmaxf(tmx, fmaxf(fmaxf(v.x, v.y), fmaxf(v.z, v.w)));
            tmn = fminf(tmn, fminf(fminf(v.x, v.y), fminf(v.z, v.w)));
        }
        block_minmax_atomic(tmn, tmx, &g_xmin_u, &g_xmax_u);
        return;
    }
    int row = blockIdx.x;
    const float4* wr = (const float4*)(w + (size_t)row * KDIM);
    float4 v[4];
    float am = 0.f;
    #pragma unroll
    for (int i = 0; i < 4; i++) {
        v[i] = wr[threadIdx.x + i * 256];
        am = fmaxf(am, fmaxf(fmaxf(fabsf(v[i].x), fabsf(v[i].y)),
                             fmaxf(fabsf(v[i].z), fabsf(v[i].w))));
    }
    #pragma unroll
    for (int o = 16; o > 0; o >>= 1) am = fmaxf(am, __shfl_xor_sync(0xffffffffu, am, o));
    __shared__ float sred[8];
    __shared__ float swsv;
    if ((threadIdx.x & 31) == 0) sred[threadIdx.x >> 5] = am;
    __syncthreads();
    if (threadIdx.x == 0) {
        for (int i = 1; i < 8; i++) am = fmaxf(am, sred[i]);
        float ws = am / 127.f;
        swsv = ws;
        g_wscale[row] = ws;
    }
    __syncthreads();
    float ws = swsv;
    #pragma unroll
    for (int i = 0; i < 4; i++) {
        int k = (threadIdx.x + i * 256) * 4;
        float q0 = fminf(fmaxf(rintf(v[i].x / ws), -127.f), 127.f);
        float q1 = fminf(fmaxf(rintf(v[i].y / ws), -127.f), 127.f);
        float q2 = fminf(fmaxf(rintf(v[i].z / ws), -127.f), 127.f);
        float q3 = fminf(fmaxf(rintf(v[i].w / ws), -127.f), 127.f);
        __nv_bfloat162 p0, p1;
        p0.x = __float2bfloat16_rn(q0); p0.y = __float2bfloat16_rn(q1);
        p1.x = __float2bfloat16_rn(q2); p1.y = __float2bfloat16_rn(q3);
        uint2 pk;
        pk.x = *(uint32_t*)&p0; pk.y = *(uint32_t*)&p1;
        *(uint2*)(g_qwt + tiled_off(row, k)) = pk;
    }
}

__global__ void params1_kernel() {
    float mx = __uint_as_float(g_xmax_u);
    float mn = __uint_as_float(g_xmin_u);
    float sc = (mx - mn) / 255.f;
    g_sc = sc;
    g_zp = rintf(-128.f - mn / sc);
}

// activation quant: 8 elems/thread -> one 16B aligned tiled-layout write per thread
__global__ void quantx_kernel(const float4* __restrict__ x4, int n8) {
    float sc = g_sc, zp = g_zp;
    for (int i = blockIdx.x * blockDim.x + threadIdx.x; i < n8; i += gridDim.x * blockDim.x) {
        int e = i * 8;
        int row = e >> 12, k = e & (KDIM - 1);
        float4 a = x4[2 * i];
        float4 b = x4[2 * i + 1];
        float q0 = fminf(fmaxf(rintf(a.x / sc) + zp, -128.f), 127.f) - zp;
        float q1 = fminf(fmaxf(rintf(a.y / sc) + zp, -128.f), 127.f) - zp;
        float q2 = fminf(fmaxf(rintf(a.z / sc) + zp, -128.f), 127.f) - zp;
        float q3 = fminf(fmaxf(rintf(a.w / sc) + zp, -128.f), 127.f) - zp;
        float q4 = fminf(fmaxf(rintf(b.x / sc) + zp, -128.f), 127.f) - zp;
        float q5 = fminf(fmaxf(rintf(b.y / sc) + zp, -128.f), 127.f) - zp;
        float q6 = fminf(fmaxf(rintf(b.z / sc) + zp, -128.f), 127.f) - zp;
        float q7 = fminf(fmaxf(rintf(b.w / sc) + zp, -128.f), 127.f) - zp;
        __nv_bfloat162 p0, p1, p2, p3;
        p0.x = __float2bfloat16_rn(q0); p0.y = __float2bfloat16_rn(q1);
        p1.x = __float2bfloat16_rn(q2); p1.y = __float2bfloat16_rn(q3);
        p2.x = __float2bfloat16_rn(q4); p2.y = __float2bfloat16_rn(q5);
        p3.x = __float2bfloat16_rn(q6); p3.y = __float2bfloat16_rn(q7);
        uint4 pk;
        pk.x = *(uint32_t*)&p0; pk.y = *(uint32_t*)&p1;
        pk.z = *(uint32_t*)&p2; pk.w = *(uint32_t*)&p3;
        // k..k+7 fills both 8B halves of one swizzled 16B chunk -> 16B store
        int tile = row >> 8, r = row & 255, ks = k >> 6, c16 = (k & 63) >> 3;
        size_t off = ((((size_t)tile * (KDIM / 64) + ks) * 256 + r) << 7) +
                     (size_t)((c16 ^ (r & 7)) << 4);
        *(uint4*)(g_qxt + off) = pk;
    }
}

// ===== tcgen05 GEMM: 256x256 tile, BK=64 bf16, 3 stages, round-13 cp.async pipeline =====
#define STAGES 3
#define STAGE_BYTES 65536
#define SMEM_STAGE0 1024
#define SMEM_QB (SMEM_STAGE0 + STAGES * STAGE_BYTES)
#define GEMM_SMEM (SMEM_QB + 256 * 4)
#define NKITER (KDIM / 64)

#if HAS_TCGEN05
__device__ __forceinline__ void load_stage(uint32_t sbase, int k0, int by, int bx, int tid) {
    const unsigned char* Ag = g_qxt + ((size_t)by * NKITER + k0) * 32768;
    const unsigned char* Bg = g_qwt + ((size_t)bx * NKITER + k0) * 32768;
    #pragma unroll
    for (int i = 0; i < 8; i++) {
        uint32_t off = (uint32_t)(tid + i * 256) * 16;   // 0..32767, identity copy
        cp16(sbase + off,         Ag + off);
        cp16(sbase + 32768 + off, Bg + off);
    }
}
#endif

__global__ void __launch_bounds__(256, 1) gemm_tc_kernel(const float* __restrict__ bias,
                                                         float* __restrict__ out) {
#if HAS_TCGEN05
    extern __shared__ __align__(1024) char ds[];
    uint32_t sb = smem_u32(ds);
    int tid = threadIdx.x, wid = tid >> 5, lane = tid & 31;
    int bx = blockIdx.x, by = blockIdx.y;
    int bm = by * 256, bn = bx * 256;

    if (wid == 0) TCGEN05_ALLOC(sb + 0, 512);
    if (tid == 0) {
        #pragma unroll
        for (int s = 0; s < STAGES; s++) MBAR_INIT(sb + 8 + s * 8, 1);
    }
    __syncthreads();
    uint32_t tb;
    asm volatile("ld.shared.b32 %0, [%1];" : "=r"(tb) : "r"(sb));

    load_stage(sb + SMEM_STAGE0 + 0 * STAGE_BYTES, 0, by, bx, tid); CP_COMMIT();
    load_stage(sb + SMEM_STAGE0 + 1 * STAGE_BYTES, 1, by, bx, tid); CP_COMMIT();

    int ph0 = 0, ph1 = 0, ph2 = 0;
    for (int k0 = 0; k0 < NKITER; k0++) {
        int s = k0 % STAGES;
        CP_WAIT1();
        FENCE_PROXY_ASYNC();
        __syncthreads();                       // stage s visible to all

        if (tid == 0) {
            uint32_t stg = sb + SMEM_STAGE0 + s * STAGE_BYTES;
            uint64_t ab = make_desc(stg);
            uint64_t bb = make_desc(stg + 32768);
            #pragma unroll
            for (int atom = 0; atom < 2; atom++)
                #pragma unroll
                for (int kk = 0; kk < 4; kk++)
                    mma_f16_ss(tb + atom * 256, ab + atom * 1024 + kk * 2, bb + kk * 2,
                               GEMM_IDESC, !(k0 == 0 && kk == 0));
            TCGEN05_COMMIT(sb + 8 + s * 8);
        }

        int kl = k0 + STAGES - 1;
        if (kl < NKITER) {
            int t = kl % STAGES;
            if (k0 > 0) {                      // WAR: slot reused, wait MMA of iter k0-1
                int ph = (t == 0) ? ph0 : (t == 1) ? ph1 : ph2;
                MBAR_WAIT_PARITY(sb + 8 + t * 8, ph);
                if (t == 0) ph0 ^= 1; else if (t == 1) ph1 ^= 1; else ph2 ^= 1;
            }
            load_stage(sb + SMEM_STAGE0 + t * STAGE_BYTES, kl, by, bx, tid);
        }
        CP_COMMIT();                           // one group per iter (possibly empty)
    }

    {   // wait for last iteration's MMAs
        int sl = (NKITER - 1) % STAGES;
        int ph = (sl == 0) ? ph0 : (sl == 1) ? ph1 : ph2;
        MBAR_WAIT_PARITY(sb + 8 + sl * 8, ph);
    }
    TCGEN05_FENCE_AFTER();

    // per-column qbias
    float sc = g_sc;
    float* qb = (float*)(ds + SMEM_QB);
    {
        int col = bn + tid;
        qb[tid] = rintf(bias[col] / (g_wscale[col] * sc));
    }
    __syncthreads();

    int atom = wid >> 2;
    int row = bm + atom * 128 + (wid & 3) * 32 + lane;
    float tmx = 0.f, tmn = 0.f;
    float* orow = out + (size_t)row * ODIM + bn;
    #pragma unroll
    for (int ch = 0; ch < 8; ch++) {
        uint32_t dr[32];
        TCGEN05_LD_X32(dr, tb + atom * 256 + ch * 32);
        TCGEN05_WAIT_LD();
        float v[32];
        #pragma unroll
        for (int c = 0; c < 32; c++) {
            float f = __uint_as_float(dr[c]) + qb[ch * 32 + c];
            v[c] = f;
            tmx = fmaxf(tmx, f);
            tmn = fminf(tmn, f);
        }
        #pragma unroll
        for (int c = 0; c < 32; c += 4)
            *(float4*)&orow[ch * 32 + c] = make_float4(v[c], v[c + 1], v[c + 2], v[c + 3]);
    }
    TCGEN05_FENCE_BEFORE();
    block_minmax_atomic(tmn, tmx, &g_rmin_u, &g_rmax_u);
    __syncthreads();
    if (wid == 0) {
        TCGEN05_RELINQ();
        TCGEN05_DEALLOC(tb, 512);
    }
#endif
}

__global__ void params2_kernel() {
    float rmx = __uint_as_float(g_rmax_u);
    float rmn = __uint_as_float(g_rmin_u);
    float resc = (rmx - rmn) / 255.f;
    g_resc = resc;
    g_rezp = rintf(-128.f - rmn / resc);
}

__global__ void requant_kernel(float4* __restrict__ out4, int n4) {
    float resc = g_resc, rezp = g_rezp, sc = g_sc;
    for (int i = blockIdx.x * blockDim.x + threadIdx.x; i < n4; i += gridDim.x * blockDim.x) {
        float4 v = out4[i];
        int col = (i * 4) & (ODIM - 1);
        float s0 = (sc * g_wscale[col])     * resc;
        float s1 = (sc * g_wscale[col + 1]) * resc;
        float s2 = (sc * g_wscale[col + 2]) * resc;
        float s3 = (sc * g_wscale[col + 3]) * resc;
        float r0 = fminf(fmaxf(rintf(v.x / resc) + rezp, -128.f), 127.f);
        float r1 = fminf(fmaxf(rintf(v.y / resc) + rezp, -128.f), 127.f);
        float r2 = fminf(fmaxf(rintf(v.z / resc) + rezp, -128.f), 127.f);
        float r3 = fminf(fmaxf(rintf(v.w / resc) + rezp, -128.f), 127.f);
        v.x = (r0 - rezp) * s0;
        v.y = (r1 - rezp) * s1;
        v.z = (r2 - rezp) * s2;
        v.w = (r3 - rezp) * s3;
        out4[i] = v;
    }
}

// ---------------- launch ----------------
extern "C" void kernel_launch(void* const* d_in, const int* in_sizes, int n_in,
                              void* d_out, int out_size) {
    const float* x    = (const float*)d_in[0];
    const float* w    = (const float*)d_in[1];
    const float* bias = (const float*)d_in[2];
    float* out = (float*)d_out;

    cudaFuncSetAttribute(gemm_tc_kernel, cudaFuncAttributeMaxDynamicSharedMemorySize, GEMM_SMEM);

    init_kernel<<<1, 1>>>();
    quantw_minmax_kernel<<<ODIM + MMX_BLOCKS, 256>>>(w, (const float4*)x, NROWS * KDIM / 4);
    params1_kernel<<<1, 1>>>();
    quantx_kernel<<<4096, 256>>>((const float4*)x, NROWS * KDIM / 8);

    dim3 grid_tc(ODIM / 256, NROWS / 256);
    gemm_tc_kernel<<<grid_tc, 256, GEMM_SMEM>>>(bias, out);

    params2_kernel<<<1, 1>>>();
    requant_kernel<<<8192, 256>>>((float4*)out, NROWS * ODIM / 4);
}